// round 1
// baseline (speedup 1.0000x reference)
#include <cuda_runtime.h>

#define S      128
#define SS     16384
#define P      882
#define AK     21
#define HP     148          // padded input spatial (128 + 20)
#define K      1681
#define LK     41
#define MR     19
#define NITERS 5

// Output layout (float32, total 14483457):
//  [0      : 16384)  raw_aff
//  [16384  : 32768)  lat (final)
//  [32768]           lat_correlations
//  [32769  : end)    x_tiles, row-major (l, p)
#define OUT_XT 32769

// ---- scratch (device globals; no allocation allowed) ----
__device__ float g_aff [SS];
__device__ float g_lat [SS];   // lat entering the sre conv
__device__ float g_latc[SS];   // lat after sre conv
__device__ float g_tmp [SS];   // lat after inhibition+relu*1.5
__device__ float g_mean[SS];   // running sum of normalized lat
__device__ float g_part[SS];   // per-pixel correlation partials

__device__ __forceinline__ int refl(int i) {
    i = (i < 0) ? -i : i;
    return (i > 127) ? (254 - i) : i;
}

// deterministic 2-value block reduction (blockDim.x == 256)
__device__ __forceinline__ void reduce2(float& a, float& b) {
    __shared__ float sa[8], sb[8];
    int lane = threadIdx.x & 31, w = threadIdx.x >> 5;
    #pragma unroll
    for (int o = 16; o > 0; o >>= 1) {
        a += __shfl_down_sync(0xffffffffu, a, o);
        b += __shfl_down_sync(0xffffffffu, b, o);
    }
    if (lane == 0) { sa[w] = a; sb[w] = b; }
    __syncthreads();
    if (w == 0) {
        a = (lane < 8) ? sa[lane] : 0.f;
        b = (lane < 8) ? sb[lane] : 0.f;
        #pragma unroll
        for (int o = 4; o > 0; o >>= 1) {
            a += __shfl_down_sync(0xffffffffu, a, o);
            b += __shfl_down_sync(0xffffffffu, b, o);
        }
    }
}

// ---------------------------------------------------------------------------
// Kernel A: x_tiles + raw_aff (+ in-pass rfs row-sum normalization) + init
// one block per pixel, 256 threads
// ---------------------------------------------------------------------------
__global__ void kA(const float* __restrict__ x, const float* __restrict__ rfs,
                   const float* __restrict__ adath, const float* __restrict__ aenv,
                   float* __restrict__ out) {
    int l = blockIdx.x;
    int y = l >> 7, c0 = l & 127;
    const float* w  = rfs + (long)l * P;
    float*       xt = out + OUT_XT + (long)l * P;
    float d1 = 0.f, d2 = 0.f;
    for (int p = threadIdx.x; p < P; p += 256) {
        int ch = (p >= 441);
        int q  = p - ch * 441;
        int di = q / AK, dj = q - di * AK;
        float xv = x[ch * (HP * HP) + (y + di) * HP + (c0 + dj)];
        float t  = xv * aenv[p];
        xt[p] = t;
        float wv = w[p];
        d1 += t * wv;
        d2 += wv;
    }
    reduce2(d1, d2);
    if (threadIdx.x == 0) {
        float inv = 1.f / d2;
        float raw = (float)P * d1 * inv;       // raw_aff = P * <xt, rfs>/sum(rfs)
        out[l]    = raw;
        float a   = d1 * inv - adath[l];        // aff = raw/P - adathresh
        g_aff[l]  = a;
        g_lat[l]  = fmaxf(a, 0.f);
        g_mean[l] = 0.f;                        // reset for graph replay
    }
}

// ---------------------------------------------------------------------------
// Kernel B: 9x9 sre conv with reflect padding (one thread per pixel)
// ---------------------------------------------------------------------------
__global__ void kB(const float* __restrict__ sre) {
    __shared__ float s[81];
    if (threadIdx.x < 81) s[threadIdx.x] = sre[threadIdx.x];
    __syncthreads();
    int l = blockIdx.x * blockDim.x + threadIdx.x;
    int y = l >> 7, x = l & 127;
    float acc = 0.f;
    #pragma unroll
    for (int i = 0; i < 9; i++) {
        int r = refl(y + i - 4) << 7;
        #pragma unroll
        for (int j = 0; j < 9; j++)
            acc += g_lat[r + refl(x + j - 4)] * s[i * 9 + j];
    }
    g_latc[l] = acc;
}

// ---------------------------------------------------------------------------
// Kernel C: lateral inhibition (the 110 MB streaming pass) + relu update
// one block per pixel, 256 threads, in-pass weight-row normalization
// ---------------------------------------------------------------------------
__global__ void kC(const float* __restrict__ latw, const float* __restrict__ lenv) {
    __shared__ float se[K];
    for (int k = threadIdx.x; k < K; k += 256) se[k] = lenv[k];
    __syncthreads();
    int l = blockIdx.x;
    int y = l >> 7, x = l & 127;
    const float* w = latw + (long)l * K;
    float num = 0.f, den = 0.f;
    for (int k = threadIdx.x; k < K; k += 256) {
        float wv = w[k];
        int di = k / LK, dj = k - di * LK;
        int r = y + di - 20, c = x + dj - 20;
        float v = ((unsigned)r < 128u && (unsigned)c < 128u) ? g_latc[(r << 7) + c] : 0.f;
        num += v * se[k] * wv;   // tiles * env_k * lat_w  (lat_w = w/rowsum)
        den += wv;
    }
    reduce2(num, den);
    if (threadIdx.x == 0) {
        float lat_neg = num / den;
        g_tmp[l] = fmaxf(g_latc[l] - lat_neg + g_aff[l], 0.f) * 1.5f;
    }
}

// ---------------------------------------------------------------------------
// Kernel D: masked 19x19 max-pool (reflect pad), normalize, accumulate mean
// ---------------------------------------------------------------------------
__global__ void kD(const float* __restrict__ mmask) {
    __shared__ float sm[MR * MR];
    for (int k = threadIdx.x; k < MR * MR; k += blockDim.x) sm[k] = mmask[k];
    __syncthreads();
    int l = blockIdx.x * blockDim.x + threadIdx.x;
    int y = l >> 7, x = l & 127;
    float m = 1.0f;   // maximum(. , 1.0)
    for (int i = 0; i < MR; i++) {
        int r = refl(y + i - 9) << 7;
        for (int j = 0; j < MR; j++) {
            if (sm[i * MR + j] > 0.f)
                m = fmaxf(m, g_tmp[r + refl(x + j - 9)]);   // lat >= 0, mask is 0/1
        }
    }
    float v = g_tmp[l] / (m + 1e-5f);
    g_lat[l]  = v;
    g_mean[l] += v;
}

// ---------------------------------------------------------------------------
// Kernel E: final correlation partials (another 110 MB pass) + copy final lat
// contrib_l = (mean/5)[l] * K * <patch(mean/5)*env, w>/rowsum = 0.04*mean*K*num/den
// ---------------------------------------------------------------------------
__global__ void kE(const float* __restrict__ latw, const float* __restrict__ lenv,
                   float* __restrict__ out) {
    __shared__ float se[K];
    for (int k = threadIdx.x; k < K; k += 256) se[k] = lenv[k];
    __syncthreads();
    int l = blockIdx.x;
    int y = l >> 7, x = l & 127;
    const float* w = latw + (long)l * K;
    float num = 0.f, den = 0.f;
    for (int k = threadIdx.x; k < K; k += 256) {
        float wv = w[k];
        int di = k / LK, dj = k - di * LK;
        int r = y + di - 20, c = x + dj - 20;
        float v = ((unsigned)r < 128u && (unsigned)c < 128u) ? g_mean[(r << 7) + c] : 0.f;
        num += v * se[k] * wv;
        den += wv;
    }
    reduce2(num, den);
    if (threadIdx.x == 0) {
        g_part[l] = 0.04f * g_mean[l] * (float)K * num / den;
        out[SS + l] = g_lat[l];   // final lat output
    }
}

// ---------------------------------------------------------------------------
// Kernel F: deterministic final reduction of correlation partials
// ---------------------------------------------------------------------------
__global__ void kF(float* __restrict__ out) {
    __shared__ float sh[512];
    float s = 0.f;
    for (int i = threadIdx.x; i < SS; i += 512) s += g_part[i];
    sh[threadIdx.x] = s;
    __syncthreads();
    for (int o = 256; o > 0; o >>= 1) {
        if (threadIdx.x < o) sh[threadIdx.x] += sh[threadIdx.x + o];
        __syncthreads();
    }
    if (threadIdx.x == 0) out[32768] = sh[0];
}

// ---------------------------------------------------------------------------
extern "C" void kernel_launch(void* const* d_in, const int* in_sizes, int n_in,
                              void* d_out, int out_size) {
    const float* x     = (const float*)d_in[0];
    const float* rfs   = (const float*)d_in[1];
    const float* latw  = (const float*)d_in[2];
    const float* adath = (const float*)d_in[3];
    const float* aenv  = (const float*)d_in[4];
    const float* sre   = (const float*)d_in[5];
    const float* lenv  = (const float*)d_in[6];
    const float* mmask = (const float*)d_in[7];
    float* out = (float*)d_out;

    kA<<<SS, 256>>>(x, rfs, adath, aenv, out);
    for (int it = 0; it < NITERS; it++) {
        kB<<<SS / 256, 256>>>(sre);
        kC<<<SS, 256>>>(latw, lenv);
        kD<<<SS / 256, 256>>>(mmask);
    }
    kE<<<SS, 256>>>(latw, lenv, out);
    kF<<<1, 512>>>(out);
}

// round 2
// speedup vs baseline: 1.5204x; 1.5204x over previous
#include <cuda_runtime.h>
#include <cuda_fp16.h>

#define S      128
#define SS     16384
#define P      882
#define AK     21
#define HP     148
#define K      1681
#define LK     41
#define MR     19
#define NITERS 5
#define PW     176          // padded field width  (20 left, 28 right)
#define PH     168          // padded field height (20 top, 20 bottom)
#define NCH    246          // weight chunks per pixel: 41 rows * 6 chunks
#define OUT_XT 32769

// ---- scratch (device globals; .bss zero-initialized; borders stay 0) ----
__device__ float g_aff [SS];
__device__ float g_lat [SS];            // field entering sre conv
__device__ float g_tmp [SS];            // field after inhibition+relu*1.5
__device__ float g_latp [PH * PW];      // zero-padded conv output
__device__ float g_meanp[PH * PW];      // zero-padded running mean-sum
__device__ float g_part[SS];
__device__ uint4 g_wn[SS * NCH];        // fp16 normalized weights, 8 per chunk (64.5 MB)

__device__ __forceinline__ int refl(int i) {
    i = (i < 0) ? -i : i;
    return (i > 127) ? (254 - i) : i;
}

// deterministic block reduction, blockDim.x == 256
__device__ __forceinline__ float reduce1(float a) {
    __shared__ float sa[8];
    int lane = threadIdx.x & 31, w = threadIdx.x >> 5;
    #pragma unroll
    for (int o = 16; o > 0; o >>= 1) a += __shfl_down_sync(0xffffffffu, a, o);
    if (lane == 0) sa[w] = a;
    __syncthreads();
    if (w == 0) {
        a = (lane < 8) ? sa[lane] : 0.f;
        #pragma unroll
        for (int o = 4; o > 0; o >>= 1) a += __shfl_down_sync(0xffffffffu, a, o);
    }
    return a;
}

__device__ __forceinline__ void reduce2(float& a, float& b) {
    __shared__ float sa[8], sb[8];
    int lane = threadIdx.x & 31, w = threadIdx.x >> 5;
    #pragma unroll
    for (int o = 16; o > 0; o >>= 1) {
        a += __shfl_down_sync(0xffffffffu, a, o);
        b += __shfl_down_sync(0xffffffffu, b, o);
    }
    if (lane == 0) { sa[w] = a; sb[w] = b; }
    __syncthreads();
    if (w == 0) {
        a = (lane < 8) ? sa[lane] : 0.f;
        b = (lane < 8) ? sb[lane] : 0.f;
        #pragma unroll
        for (int o = 4; o > 0; o >>= 1) {
            a += __shfl_down_sync(0xffffffffu, a, o);
            b += __shfl_down_sync(0xffffffffu, b, o);
        }
    }
}

// ---------------------------------------------------------------------------
// kA: x_tiles + raw_aff (+ in-pass rfs normalization) + per-launch init
// ---------------------------------------------------------------------------
__global__ void kA(const float* __restrict__ x, const float* __restrict__ rfs,
                   const float* __restrict__ adath, const float* __restrict__ aenv,
                   float* __restrict__ out) {
    int l = blockIdx.x;
    int y = l >> 7, c0 = l & 127;
    const float* w  = rfs + (long)l * P;
    float*       xt = out + OUT_XT + (long)l * P;
    float d1 = 0.f, d2 = 0.f;
    for (int p = threadIdx.x; p < P; p += 256) {
        int ch = (p >= 441);
        int q  = p - ch * 441;
        int di = q / AK, dj = q - di * AK;
        float xv = x[ch * (HP * HP) + (y + di) * HP + (c0 + dj)];
        float t  = xv * aenv[p];
        xt[p] = t;
        float wv = w[p];
        d1 += t * wv;
        d2 += wv;
    }
    reduce2(d1, d2);
    if (threadIdx.x == 0) {
        float inv = 1.f / d2;
        float raw = (float)P * d1 * inv;
        out[l]    = raw;
        float a   = d1 * inv - adath[l];
        g_aff[l]  = a;
        g_lat[l]  = fmaxf(a, 0.f);
        g_meanp[(y + 20) * PW + c0 + 20] = 0.f;   // reset for graph replay
    }
}

// ---------------------------------------------------------------------------
// kW: fold env & row-normalization into fp16 weights, padded-chunk layout
// ws[k] = K * w[k] * env[k] / rowsum(w),  rows of 41 padded to 48
// ---------------------------------------------------------------------------
__global__ void kW(const float* __restrict__ latw, const float* __restrict__ lenv) {
    int l = blockIdx.x;
    const float* w = latw + (long)l * K;
    float s = 0.f;
    for (int k = threadIdx.x; k < K; k += 256) s += w[k];
    s = reduce1(s);
    __shared__ float ssum;
    if (threadIdx.x == 0) ssum = s;
    __syncthreads();
    float inv = (float)K / ssum;
    int t = threadIdx.x;
    if (t < NCH) {
        int di = t / 6, djc = (t - (t / 6) * 6) * 8;
        float v[8];
        #pragma unroll
        for (int j = 0; j < 8; j++) {
            int dj = djc + j;
            int k  = di * LK + dj;
            v[j] = (dj < LK) ? w[k] * lenv[k] * inv : 0.f;
        }
        __half2 h0 = __floats2half2_rn(v[0], v[1]);
        __half2 h1 = __floats2half2_rn(v[2], v[3]);
        __half2 h2 = __floats2half2_rn(v[4], v[5]);
        __half2 h3 = __floats2half2_rn(v[6], v[7]);
        uint4 o;
        o.x = *(unsigned*)&h0; o.y = *(unsigned*)&h1;
        o.z = *(unsigned*)&h2; o.w = *(unsigned*)&h3;
        g_wn[(long)l * NCH + t] = o;
    }
}

// ---------------------------------------------------------------------------
// kB: 9x9 sre conv, reflect pad, smem-tiled; writes zero-padded g_latp
// grid (8,8), block 256 (16x16 tile)
// ---------------------------------------------------------------------------
__global__ void kB(const float* __restrict__ sre) {
    __shared__ float sk[81];
    __shared__ float tile[24][25];
    if (threadIdx.x < 81) sk[threadIdx.x] = sre[threadIdx.x];
    int bx = blockIdx.x * 16, by = blockIdx.y * 16;
    for (int idx = threadIdx.x; idx < 576; idx += 256) {
        int r = idx / 24, c = idx - r * 24;
        tile[r][c] = g_lat[(refl(by + r - 4) << 7) + refl(bx + c - 4)];
    }
    __syncthreads();
    int tx = threadIdx.x & 15, ty = threadIdx.x >> 4;
    float acc = 0.f;
    #pragma unroll
    for (int i = 0; i < 9; i++)
        #pragma unroll
        for (int j = 0; j < 9; j++)
            acc += tile[ty + i][tx + j] * sk[i * 9 + j];
    g_latp[(by + ty + 20) * PW + (bx + tx + 20)] = acc;
}

// ---------------------------------------------------------------------------
// kC: lateral inhibition, fp16 weights, padded gather (no bounds checks)
// one block per pixel, 256 threads (246 active chunks)
// ---------------------------------------------------------------------------
__global__ void kC() {
    int l = blockIdx.x;
    int y = l >> 7, x = l & 127;
    int t = threadIdx.x;
    float acc = 0.f;
    if (t < NCH) {
        int di = t / 6, djc = (t - (t / 6) * 6) * 8;
        uint4 wv = g_wn[(long)l * NCH + t];
        const float* lp = g_latp + (y + di) * PW + x + djc;
        float2 a = __half22float2(*(__half2*)&wv.x);
        float2 b = __half22float2(*(__half2*)&wv.y);
        float2 c = __half22float2(*(__half2*)&wv.z);
        float2 d = __half22float2(*(__half2*)&wv.w);
        acc = a.x * lp[0] + a.y * lp[1] + b.x * lp[2] + b.y * lp[3]
            + c.x * lp[4] + c.y * lp[5] + d.x * lp[6] + d.y * lp[7];
    }
    acc = reduce1(acc);
    if (t == 0) {
        float latc = g_latp[(y + 20) * PW + x + 20];
        g_tmp[l] = fmaxf(latc - acc * (1.f / (float)K) + g_aff[l], 0.f) * 1.5f;
    }
}

// ---------------------------------------------------------------------------
// kD: masked 19x19 max-pool (reflect), smem-tiled with circle row-extents;
// normalize, update g_lat and accumulate g_meanp. grid (8,8), block 256
// ---------------------------------------------------------------------------
__global__ void kD() {
    __shared__ float tile[34][35];
    int bx = blockIdx.x * 16, by = blockIdx.y * 16;
    for (int idx = threadIdx.x; idx < 34 * 34; idx += 256) {
        int r = idx / 34, c = idx - r * 34;
        tile[r][c] = g_tmp[(refl(by + r - 9) << 7) + refl(bx + c - 9)];
    }
    __syncthreads();
    int tx = threadIdx.x & 15, ty = threadIdx.x >> 4;
    float m = 1.0f;
    #pragma unroll
    for (int i = 0; i < MR; i++) {
        int rdi = i - 9;
        int e = (int)sqrtf(90.25f - (float)(rdi * rdi));   // circle row extent
        const float* row = &tile[ty + i][tx + 9];
        for (int j = -e; j <= e; j++) m = fmaxf(m, row[j]);
    }
    float v = tile[ty + 9][tx + 9] / (m + 1e-5f);
    int y = by + ty, x = bx + tx;
    g_lat[(y << 7) + x] = v;
    g_meanp[(y + 20) * PW + (x + 20)] += v;
}

// ---------------------------------------------------------------------------
// kE: final correlation partials (gather on padded mean field) + final lat out
// ---------------------------------------------------------------------------
__global__ void kE(float* __restrict__ out) {
    int l = blockIdx.x;
    int y = l >> 7, x = l & 127;
    int t = threadIdx.x;
    float acc = 0.f;
    if (t < NCH) {
        int di = t / 6, djc = (t - (t / 6) * 6) * 8;
        uint4 wv = g_wn[(long)l * NCH + t];
        const float* lp = g_meanp + (y + di) * PW + x + djc;
        float2 a = __half22float2(*(__half2*)&wv.x);
        float2 b = __half22float2(*(__half2*)&wv.y);
        float2 c = __half22float2(*(__half2*)&wv.z);
        float2 d = __half22float2(*(__half2*)&wv.w);
        acc = a.x * lp[0] + a.y * lp[1] + b.x * lp[2] + b.y * lp[3]
            + c.x * lp[4] + c.y * lp[5] + d.x * lp[6] + d.y * lp[7];
    }
    acc = reduce1(acc);
    if (t == 0) {
        float mc = g_meanp[(y + 20) * PW + x + 20];
        g_part[l] = 0.04f * mc * acc;       // (1/ITERS)^2 = 0.04
        out[SS + l] = g_lat[l];
    }
}

// ---------------------------------------------------------------------------
__global__ void kF(float* __restrict__ out) {
    __shared__ float sh[512];
    float s = 0.f;
    for (int i = threadIdx.x; i < SS; i += 512) s += g_part[i];
    sh[threadIdx.x] = s;
    __syncthreads();
    for (int o = 256; o > 0; o >>= 1) {
        if (threadIdx.x < o) sh[threadIdx.x] += sh[threadIdx.x + o];
        __syncthreads();
    }
    if (threadIdx.x == 0) out[32768] = sh[0];
}

// ---------------------------------------------------------------------------
extern "C" void kernel_launch(void* const* d_in, const int* in_sizes, int n_in,
                              void* d_out, int out_size) {
    const float* x     = (const float*)d_in[0];
    const float* rfs   = (const float*)d_in[1];
    const float* latw  = (const float*)d_in[2];
    const float* adath = (const float*)d_in[3];
    const float* aenv  = (const float*)d_in[4];
    const float* sre   = (const float*)d_in[5];
    const float* lenv  = (const float*)d_in[6];
    float* out = (float*)d_out;

    kA<<<SS, 256>>>(x, rfs, adath, aenv, out);
    kW<<<SS, 256>>>(latw, lenv);
    for (int it = 0; it < NITERS; it++) {
        kB<<<dim3(8, 8), 256>>>(sre);
        kC<<<SS, 256>>>();
        kD<<<dim3(8, 8), 256>>>();
    }
    kE<<<SS, 256>>>(out);
    kF<<<1, 512>>>(out);
}

// round 3
// speedup vs baseline: 1.5224x; 1.0013x over previous
#include <cuda_runtime.h>
#include <cuda_fp16.h>

#define S      128
#define SS     16384
#define P      882
#define AK     21
#define HP     148
#define K      1681
#define LK     41
#define MR     19
#define NITERS 5
#define PW     176          // padded field width  (20 left, 28 right)
#define PH     168          // padded field height (20 top, 20 bottom)
#define NCH    246          // weight chunks per pixel: 41 rows * 6 chunks
#define OUT_XT 32769

// ---- scratch (device globals; .bss zero-initialized; borders stay 0) ----
__device__ float g_aff [SS];
__device__ float g_lat [SS];            // field entering sre conv
__device__ float g_tmp [SS];            // field after inhibition+relu*1.5
__device__ float g_latp [PH * PW];      // zero-padded conv output
__device__ float g_meanp[PH * PW];      // zero-padded running mean-sum
__device__ float g_part[SS];
__device__ uint4 g_wn[SS * NCH];        // fp16 normalized weights, 8 per chunk (64.5 MB)

__device__ __forceinline__ int refl(int i) {
    i = (i < 0) ? -i : i;
    return (i > 127) ? (254 - i) : i;
}

// deterministic block reduction, blockDim.x == 256
__device__ __forceinline__ float reduce1(float a) {
    __shared__ float sa[8];
    int lane = threadIdx.x & 31, w = threadIdx.x >> 5;
    #pragma unroll
    for (int o = 16; o > 0; o >>= 1) a += __shfl_down_sync(0xffffffffu, a, o);
    if (lane == 0) sa[w] = a;
    __syncthreads();
    if (w == 0) {
        a = (lane < 8) ? sa[lane] : 0.f;
        #pragma unroll
        for (int o = 4; o > 0; o >>= 1) a += __shfl_down_sync(0xffffffffu, a, o);
    }
    return a;
}

__device__ __forceinline__ void reduce2(float& a, float& b) {
    __shared__ float sa[8], sb[8];
    int lane = threadIdx.x & 31, w = threadIdx.x >> 5;
    #pragma unroll
    for (int o = 16; o > 0; o >>= 1) {
        a += __shfl_down_sync(0xffffffffu, a, o);
        b += __shfl_down_sync(0xffffffffu, b, o);
    }
    if (lane == 0) { sa[w] = a; sb[w] = b; }
    __syncthreads();
    if (w == 0) {
        a = (lane < 8) ? sa[lane] : 0.f;
        b = (lane < 8) ? sb[lane] : 0.f;
        #pragma unroll
        for (int o = 4; o > 0; o >>= 1) {
            a += __shfl_down_sync(0xffffffffu, a, o);
            b += __shfl_down_sync(0xffffffffu, b, o);
        }
    }
}

// ---------------------------------------------------------------------------
// kA: x_tiles + raw_aff (+ in-pass rfs normalization) + per-launch init
// ---------------------------------------------------------------------------
__global__ void kA(const float* __restrict__ x, const float* __restrict__ rfs,
                   const float* __restrict__ adath, const float* __restrict__ aenv,
                   float* __restrict__ out) {
    int l = blockIdx.x;
    int y = l >> 7, c0 = l & 127;
    const float* w  = rfs + (long)l * P;
    float*       xt = out + OUT_XT + (long)l * P;
    float d1 = 0.f, d2 = 0.f;
    for (int p = threadIdx.x; p < P; p += 256) {
        int ch = (p >= 441);
        int q  = p - ch * 441;
        int di = q / AK, dj = q - di * AK;
        float xv = x[ch * (HP * HP) + (y + di) * HP + (c0 + dj)];
        float t  = xv * aenv[p];
        xt[p] = t;
        float wv = w[p];
        d1 += t * wv;
        d2 += wv;
    }
    reduce2(d1, d2);
    if (threadIdx.x == 0) {
        float inv = 1.f / d2;
        float raw = (float)P * d1 * inv;
        out[l]    = raw;
        float a   = d1 * inv - adath[l];
        g_aff[l]  = a;
        g_lat[l]  = fmaxf(a, 0.f);
        g_meanp[(y + 20) * PW + c0 + 20] = 0.f;   // reset for graph replay
    }
}

// ---------------------------------------------------------------------------
// kW: fold env & row-normalization into fp16 weights, padded-chunk layout
// ws[k] = K * w[k] * env[k] / rowsum(w),  rows of 41 padded to 48
// ---------------------------------------------------------------------------
__global__ void kW(const float* __restrict__ latw, const float* __restrict__ lenv) {
    int l = blockIdx.x;
    const float* w = latw + (long)l * K;
    float s = 0.f;
    for (int k = threadIdx.x; k < K; k += 256) s += w[k];
    s = reduce1(s);
    __shared__ float ssum;
    if (threadIdx.x == 0) ssum = s;
    __syncthreads();
    float inv = (float)K / ssum;
    int t = threadIdx.x;
    if (t < NCH) {
        int di = t / 6, djc = (t - (t / 6) * 6) * 8;
        float v[8];
        #pragma unroll
        for (int j = 0; j < 8; j++) {
            int dj = djc + j;
            int k  = di * LK + dj;
            v[j] = (dj < LK) ? w[k] * lenv[k] * inv : 0.f;
        }
        __half2 h0 = __floats2half2_rn(v[0], v[1]);
        __half2 h1 = __floats2half2_rn(v[2], v[3]);
        __half2 h2 = __floats2half2_rn(v[4], v[5]);
        __half2 h3 = __floats2half2_rn(v[6], v[7]);
        uint4 o;
        o.x = *(unsigned*)&h0; o.y = *(unsigned*)&h1;
        o.z = *(unsigned*)&h2; o.w = *(unsigned*)&h3;
        g_wn[(long)l * NCH + t] = o;
    }
}

// ---------------------------------------------------------------------------
// kB: 9x9 sre conv, reflect pad, smem-tiled; writes zero-padded g_latp
// grid (8,8), block 256 (16x16 tile)
// ---------------------------------------------------------------------------
__global__ void kB(const float* __restrict__ sre) {
    __shared__ float sk[81];
    __shared__ float tile[24][25];
    if (threadIdx.x < 81) sk[threadIdx.x] = sre[threadIdx.x];
    int bx = blockIdx.x * 16, by = blockIdx.y * 16;
    for (int idx = threadIdx.x; idx < 576; idx += 256) {
        int r = idx / 24, c = idx - r * 24;
        tile[r][c] = g_lat[(refl(by + r - 4) << 7) + refl(bx + c - 4)];
    }
    __syncthreads();
    int tx = threadIdx.x & 15, ty = threadIdx.x >> 4;
    float acc = 0.f;
    #pragma unroll
    for (int i = 0; i < 9; i++)
        #pragma unroll
        for (int j = 0; j < 9; j++)
            acc += tile[ty + i][tx + j] * sk[i * 9 + j];
    g_latp[(by + ty + 20) * PW + (bx + tx + 20)] = acc;
}

// ---------------------------------------------------------------------------
// kC: lateral inhibition, fp16 weights, padded gather (no bounds checks)
// one block per pixel, 256 threads (246 active chunks)
// ---------------------------------------------------------------------------
__global__ void kC() {
    int l = blockIdx.x;
    int y = l >> 7, x = l & 127;
    int t = threadIdx.x;
    float acc = 0.f;
    if (t < NCH) {
        int di = t / 6, djc = (t - (t / 6) * 6) * 8;
        uint4 wv = g_wn[(long)l * NCH + t];
        const float* lp = g_latp + (y + di) * PW + x + djc;
        float2 a = __half22float2(*(__half2*)&wv.x);
        float2 b = __half22float2(*(__half2*)&wv.y);
        float2 c = __half22float2(*(__half2*)&wv.z);
        float2 d = __half22float2(*(__half2*)&wv.w);
        acc = a.x * lp[0] + a.y * lp[1] + b.x * lp[2] + b.y * lp[3]
            + c.x * lp[4] + c.y * lp[5] + d.x * lp[6] + d.y * lp[7];
    }
    acc = reduce1(acc);
    if (t == 0) {
        float latc = g_latp[(y + 20) * PW + x + 20];
        g_tmp[l] = fmaxf(latc - acc * (1.f / (float)K) + g_aff[l], 0.f) * 1.5f;
    }
}

// ---------------------------------------------------------------------------
// kD: masked 19x19 max-pool (reflect), smem-tiled with circle row-extents;
// normalize, update g_lat and accumulate g_meanp. grid (8,8), block 256
// ---------------------------------------------------------------------------
__global__ void kD() {
    __shared__ float tile[34][35];
    int bx = blockIdx.x * 16, by = blockIdx.y * 16;
    for (int idx = threadIdx.x; idx < 34 * 34; idx += 256) {
        int r = idx / 34, c = idx - r * 34;
        tile[r][c] = g_tmp[(refl(by + r - 9) << 7) + refl(bx + c - 9)];
    }
    __syncthreads();
    int tx = threadIdx.x & 15, ty = threadIdx.x >> 4;
    float m = 1.0f;
    #pragma unroll
    for (int i = 0; i < MR; i++) {
        int rdi = i - 9;
        int e = (int)sqrtf(90.25f - (float)(rdi * rdi));   // circle row extent
        const float* row = &tile[ty + i][tx + 9];
        for (int j = -e; j <= e; j++) m = fmaxf(m, row[j]);
    }
    float v = tile[ty + 9][tx + 9] / (m + 1e-5f);
    int y = by + ty, x = bx + tx;
    g_lat[(y << 7) + x] = v;
    g_meanp[(y + 20) * PW + (x + 20)] += v;
}

// ---------------------------------------------------------------------------
// kE: final correlation partials (gather on padded mean field) + final lat out
// ---------------------------------------------------------------------------
__global__ void kE(float* __restrict__ out) {
    int l = blockIdx.x;
    int y = l >> 7, x = l & 127;
    int t = threadIdx.x;
    float acc = 0.f;
    if (t < NCH) {
        int di = t / 6, djc = (t - (t / 6) * 6) * 8;
        uint4 wv = g_wn[(long)l * NCH + t];
        const float* lp = g_meanp + (y + di) * PW + x + djc;
        float2 a = __half22float2(*(__half2*)&wv.x);
        float2 b = __half22float2(*(__half2*)&wv.y);
        float2 c = __half22float2(*(__half2*)&wv.z);
        float2 d = __half22float2(*(__half2*)&wv.w);
        acc = a.x * lp[0] + a.y * lp[1] + b.x * lp[2] + b.y * lp[3]
            + c.x * lp[4] + c.y * lp[5] + d.x * lp[6] + d.y * lp[7];
    }
    acc = reduce1(acc);
    if (t == 0) {
        float mc = g_meanp[(y + 20) * PW + x + 20];
        g_part[l] = 0.04f * mc * acc;       // (1/ITERS)^2 = 0.04
        out[SS + l] = g_lat[l];
    }
}

// ---------------------------------------------------------------------------
__global__ void kF(float* __restrict__ out) {
    __shared__ float sh[512];
    float s = 0.f;
    for (int i = threadIdx.x; i < SS; i += 512) s += g_part[i];
    sh[threadIdx.x] = s;
    __syncthreads();
    for (int o = 256; o > 0; o >>= 1) {
        if (threadIdx.x < o) sh[threadIdx.x] += sh[threadIdx.x + o];
        __syncthreads();
    }
    if (threadIdx.x == 0) out[32768] = sh[0];
}

// ---------------------------------------------------------------------------
extern "C" void kernel_launch(void* const* d_in, const int* in_sizes, int n_in,
                              void* d_out, int out_size) {
    const float* x     = (const float*)d_in[0];
    const float* rfs   = (const float*)d_in[1];
    const float* latw  = (const float*)d_in[2];
    const float* adath = (const float*)d_in[3];
    const float* aenv  = (const float*)d_in[4];
    const float* sre   = (const float*)d_in[5];
    const float* lenv  = (const float*)d_in[6];
    float* out = (float*)d_out;

    kA<<<SS, 256>>>(x, rfs, adath, aenv, out);
    kW<<<SS, 256>>>(latw, lenv);
    for (int it = 0; it < NITERS; it++) {
        kB<<<dim3(8, 8), 256>>>(sre);
        kC<<<SS, 256>>>();
        kD<<<dim3(8, 8), 256>>>();
    }
    kE<<<SS, 256>>>(out);
    kF<<<1, 512>>>(out);
}

// round 4
// speedup vs baseline: 2.1083x; 1.3849x over previous
#include <cuda_runtime.h>
#include <cuda_fp16.h>

#define S      128
#define SS     16384
#define P      882
#define AK     21
#define HP     148
#define K      1681
#define LK     41
#define MR     19
#define NITERS 5
#define PW     176          // padded field width  (20 left, 28 right)
#define PH     168          // padded field height (20 top, 20 bottom)
#define NW2    1024         // half2 weight slots per pixel (41*24=984 valid)
#define NW2V   984
#define OUT_XT 32769

// ---- scratch (device globals; .bss zero-initialized; borders stay 0) ----
__device__ float g_aff [SS];
__device__ float g_lat [SS];            // field entering sre conv
__device__ float g_tmp [SS];            // field after inhibition+relu*1.5
__device__ float g_latp [PH * PW];      // zero-padded conv output
__device__ float g_meanp[PH * PW];      // zero-padded running mean-sum
__device__ float g_part[SS];
__device__ __half2 g_wh[(long)SS * NW2]; // fp16 normalized weights (67 MB)

__device__ __forceinline__ int refl(int i) {
    i = (i < 0) ? -i : i;
    return (i > 127) ? (254 - i) : i;
}

// deterministic block reduction, blockDim.x == 256
__device__ __forceinline__ float reduce1(float a) {
    __shared__ float sa[8];
    int lane = threadIdx.x & 31, w = threadIdx.x >> 5;
    #pragma unroll
    for (int o = 16; o > 0; o >>= 1) a += __shfl_down_sync(0xffffffffu, a, o);
    if (lane == 0) sa[w] = a;
    __syncthreads();
    if (w == 0) {
        a = (lane < 8) ? sa[lane] : 0.f;
        #pragma unroll
        for (int o = 4; o > 0; o >>= 1) a += __shfl_down_sync(0xffffffffu, a, o);
    }
    return a;
}

__device__ __forceinline__ void reduce2(float& a, float& b) {
    __shared__ float sa[8], sb[8];
    int lane = threadIdx.x & 31, w = threadIdx.x >> 5;
    #pragma unroll
    for (int o = 16; o > 0; o >>= 1) {
        a += __shfl_down_sync(0xffffffffu, a, o);
        b += __shfl_down_sync(0xffffffffu, b, o);
    }
    if (lane == 0) { sa[w] = a; sb[w] = b; }
    __syncthreads();
    if (w == 0) {
        a = (lane < 8) ? sa[lane] : 0.f;
        b = (lane < 8) ? sb[lane] : 0.f;
        #pragma unroll
        for (int o = 4; o > 0; o >>= 1) {
            a += __shfl_down_sync(0xffffffffu, a, o);
            b += __shfl_down_sync(0xffffffffu, b, o);
        }
    }
}

// ---------------------------------------------------------------------------
// kA: x_tiles + raw_aff (+ in-pass rfs normalization) + per-launch init
// ---------------------------------------------------------------------------
__global__ void kA(const float* __restrict__ x, const float* __restrict__ rfs,
                   const float* __restrict__ adath, const float* __restrict__ aenv,
                   float* __restrict__ out) {
    int l = blockIdx.x;
    int y = l >> 7, c0 = l & 127;
    const float* w  = rfs + (long)l * P;
    float*       xt = out + OUT_XT + (long)l * P;
    float d1 = 0.f, d2 = 0.f;
    for (int p = threadIdx.x; p < P; p += 256) {
        int ch = (p >= 441);
        int q  = p - ch * 441;
        int di = q / AK, dj = q - di * AK;
        float xv = x[ch * (HP * HP) + (y + di) * HP + (c0 + dj)];
        float t  = xv * aenv[p];
        xt[p] = t;
        float wv = w[p];
        d1 += t * wv;
        d2 += wv;
    }
    reduce2(d1, d2);
    if (threadIdx.x == 0) {
        float inv = 1.f / d2;
        float raw = (float)P * d1 * inv;
        out[l]    = raw;
        float a   = d1 * inv - adath[l];
        g_aff[l]  = a;
        g_lat[l]  = fmaxf(a, 0.f);
        g_meanp[(y + 20) * PW + c0 + 20] = 0.f;   // reset for graph replay
    }
}

// ---------------------------------------------------------------------------
// kW: fold env & row-normalization into fp16 weights, coalesced half2 layout
// slot idx2 in [0,1024): di = idx2/24, (dj0,dj1) = (2*(idx2%24), +1)
// ws[k] = K * w[k] * env[k] / rowsum(w)
// ---------------------------------------------------------------------------
__global__ void kW(const float* __restrict__ latw, const float* __restrict__ lenv) {
    int l = blockIdx.x;
    const float* w = latw + (long)l * K;
    float s = 0.f;
    for (int k = threadIdx.x; k < K; k += 256) s += w[k];
    s = reduce1(s);
    __shared__ float ssum;
    if (threadIdx.x == 0) ssum = s;
    __syncthreads();
    float inv = (float)K / ssum;
    __half2* wp = g_wh + (long)l * NW2;
    #pragma unroll
    for (int i = 0; i < 4; i++) {
        int idx2 = i * 256 + threadIdx.x;
        int di = idx2 / 24, c = idx2 - di * 24;
        int dj0 = 2 * c, dj1 = dj0 + 1;
        float v0 = 0.f, v1 = 0.f;
        if (idx2 < NW2V) {
            int k0 = di * LK + dj0;
            if (dj0 < LK) v0 = w[k0] * lenv[k0] * inv;
            if (dj1 < LK) v1 = w[k0 + 1] * lenv[k0 + 1] * inv;
        }
        wp[idx2] = __floats2half2_rn(v0, v1);
    }
}

// ---------------------------------------------------------------------------
// kB: 9x9 sre conv, reflect pad, smem-tiled; writes zero-padded g_latp
// ---------------------------------------------------------------------------
__global__ void kB(const float* __restrict__ sre) {
    __shared__ float sk[81];
    __shared__ float tile[24][25];
    if (threadIdx.x < 81) sk[threadIdx.x] = sre[threadIdx.x];
    int bx = blockIdx.x * 16, by = blockIdx.y * 16;
    for (int idx = threadIdx.x; idx < 576; idx += 256) {
        int r = idx / 24, c = idx - r * 24;
        tile[r][c] = g_lat[(refl(by + r - 4) << 7) + refl(bx + c - 4)];
    }
    __syncthreads();
    int tx = threadIdx.x & 15, ty = threadIdx.x >> 4;
    float acc = 0.f;
    #pragma unroll
    for (int i = 0; i < 9; i++)
        #pragma unroll
        for (int j = 0; j < 9; j++)
            acc += tile[ty + i][tx + j] * sk[i * 9 + j];
    g_latp[(by + ty + 20) * PW + (bx + tx + 20)] = acc;
}

// ---------------------------------------------------------------------------
// kC: lateral inhibition; coalesced half2 weights + coalesced field gather
// one block per pixel, 256 threads, 4 half2-iterations each
// ---------------------------------------------------------------------------
__global__ void kC() {
    int l = blockIdx.x;
    int y = l >> 7, x = l & 127;
    const __half2* wp = g_wh + (long)l * NW2;
    const float* fp = g_latp + (y * PW + x);
    float acc = 0.f;
    #pragma unroll
    for (int i = 0; i < 4; i++) {
        int idx2 = i * 256 + threadIdx.x;
        if (idx2 < NW2V) {
            int di = idx2 / 24, c = idx2 - di * 24;
            const float* row = fp + di * PW + 2 * c;
            float2 wv = __half22float2(wp[idx2]);
            acc += wv.x * row[0] + wv.y * row[1];
        }
    }
    acc = reduce1(acc);
    if (threadIdx.x == 0) {
        float latc = fp[20 * PW + 20];
        g_tmp[l] = fmaxf(latc - acc * (1.f / (float)K) + g_aff[l], 0.f) * 1.5f;
    }
}

// ---------------------------------------------------------------------------
// kD: masked 19x19 max-pool (reflect), smem-tiled with circle row-extents
// ---------------------------------------------------------------------------
__global__ void kD() {
    __shared__ float tile[34][35];
    int bx = blockIdx.x * 16, by = blockIdx.y * 16;
    for (int idx = threadIdx.x; idx < 34 * 34; idx += 256) {
        int r = idx / 34, c = idx - r * 34;
        tile[r][c] = g_tmp[(refl(by + r - 9) << 7) + refl(bx + c - 9)];
    }
    __syncthreads();
    int tx = threadIdx.x & 15, ty = threadIdx.x >> 4;
    float m = 1.0f;
    #pragma unroll
    for (int i = 0; i < MR; i++) {
        int rdi = i - 9;
        int e = (int)sqrtf(90.25f - (float)(rdi * rdi));
        const float* row = &tile[ty + i][tx + 9];
        for (int j = -e; j <= e; j++) m = fmaxf(m, row[j]);
    }
    float v = tile[ty + 9][tx + 9] / (m + 1e-5f);
    int y = by + ty, x = bx + tx;
    g_lat[(y << 7) + x] = v;
    g_meanp[(y + 20) * PW + (x + 20)] += v;
}

// ---------------------------------------------------------------------------
// kE: final correlation partials (gather on padded mean field) + final lat out
// ---------------------------------------------------------------------------
__global__ void kE(float* __restrict__ out) {
    int l = blockIdx.x;
    int y = l >> 7, x = l & 127;
    const __half2* wp = g_wh + (long)l * NW2;
    const float* fp = g_meanp + (y * PW + x);
    float acc = 0.f;
    #pragma unroll
    for (int i = 0; i < 4; i++) {
        int idx2 = i * 256 + threadIdx.x;
        if (idx2 < NW2V) {
            int di = idx2 / 24, c = idx2 - di * 24;
            const float* row = fp + di * PW + 2 * c;
            float2 wv = __half22float2(wp[idx2]);
            acc += wv.x * row[0] + wv.y * row[1];
        }
    }
    acc = reduce1(acc);
    if (threadIdx.x == 0) {
        float mc = fp[20 * PW + 20];
        g_part[l] = 0.04f * mc * acc;       // (1/ITERS)^2 = 0.04
        out[SS + l] = g_lat[l];
    }
}

// ---------------------------------------------------------------------------
__global__ void kF(float* __restrict__ out) {
    __shared__ float sh[512];
    float s = 0.f;
    for (int i = threadIdx.x; i < SS; i += 512) s += g_part[i];
    sh[threadIdx.x] = s;
    __syncthreads();
    for (int o = 256; o > 0; o >>= 1) {
        if (threadIdx.x < o) sh[threadIdx.x] += sh[threadIdx.x + o];
        __syncthreads();
    }
    if (threadIdx.x == 0) out[32768] = sh[0];
}

// ---------------------------------------------------------------------------
extern "C" void kernel_launch(void* const* d_in, const int* in_sizes, int n_in,
                              void* d_out, int out_size) {
    const float* x     = (const float*)d_in[0];
    const float* rfs   = (const float*)d_in[1];
    const float* latw  = (const float*)d_in[2];
    const float* adath = (const float*)d_in[3];
    const float* aenv  = (const float*)d_in[4];
    const float* sre   = (const float*)d_in[5];
    const float* lenv  = (const float*)d_in[6];
    float* out = (float*)d_out;

    kA<<<SS, 256>>>(x, rfs, adath, aenv, out);
    kW<<<SS, 256>>>(latw, lenv);
    for (int it = 0; it < NITERS; it++) {
        kB<<<dim3(8, 8), 256>>>(sre);
        kC<<<SS, 256>>>();
        kD<<<dim3(8, 8), 256>>>();
    }
    kE<<<SS, 256>>>(out);
    kF<<<1, 512>>>(out);
}